// round 17
// baseline (speedup 1.0000x reference)
#include <cuda_runtime.h>

// Problem constants (fixed by the reference: B=8, N=4096, D=2)
#define BQ       8
#define NPTS     4096
#define NSETS    16                  // 8 batches x {y_true, y_pred}
#define NBINS    512
#define XMAX     5.0f
#define BINW     (2.0f * XMAX / NBINS)
#define BSCALE   (NBINS / (2.0f * XMAX))
#define PTHREADS 512
#define STHREADS 512
#define FTHREADS 1024
#define WIN      128                 // fixed candidate window (compile-time trips)

// Scratch (device globals — allocation-free per harness rules)
__device__ float2 g_pts[NSETS][NPTS];    // bin-sorted points (within-bin order arbitrary)
__device__ int    g_sidx[NSETS][NPTS];   // original index of each sorted slot
__device__ int    g_binStart[NSETS][NBINS + 1];
__device__ float  g_best[NSETS][NPTS];   // NN d^2 per ORIGINAL index (deterministic)
__device__ float  g_emd[NSETS];          // per-set EMD partials (t==1 slots are 0)

__device__ __forceinline__ int binOf(float x) {
    int b = (int)((x + XMAX) * BSCALE);
    return min(max(b, 0), NBINS - 1);
}
__device__ __forceinline__ float binEdge(int b) {   // left edge of bin b
    return -XMAX + (float)b * BINW;
}

// ───────── Kernel A: EMD partial + counting sort by x-bin (index carried) ────
// Within-bin order is atomic-order-dependent, but per-bin SETS are
// deterministic; search certifies the EXACT global min (unique value) and
// writes it back by original index, so the output is bit-deterministic.
__global__ __launch_bounds__(PTHREADS, 1)
void prep_kernel(const float* __restrict__ yt, const float* __restrict__ yp) {
    __shared__ int   hist[NBINS];       // histogram, then scatter cursors
    __shared__ int   scn[NBINS];        // scan workspace
    __shared__ int   start[NBINS + 1];  // exclusive prefix
    __shared__ float red[PTHREADS];

    const int tid = threadIdx.x;
    const int s   = blockIdx.x;
    const int t   = s & 1;
    const int b   = s >> 1;
    const float2* src = reinterpret_cast<const float2*>((t ? yp : yt)) + (size_t)b * NPTS;

    // EMD partial (index-aligned pairs); t==0 blocks compute, t==1 write 0.
    float e = 0.0f;
    if (t == 0) {
        const float2* T = reinterpret_cast<const float2*>(yt) + (size_t)b * NPTS;
        const float2* P = reinterpret_cast<const float2*>(yp) + (size_t)b * NPTS;
        for (int i = tid; i < NPTS; i += PTHREADS) {
            const float2 tv = T[i], pv = P[i];
            const float d0 = tv.x - pv.x;
            const float d1 = (tv.x + tv.y) - (pv.x + pv.y);
            e = fmaf(d0, d0, e);
            e = fmaf(d1, d1, e);
        }
    }
    red[tid] = e;
    __syncthreads();
    for (int w = PTHREADS / 2; w > 0; w >>= 1) {
        if (tid < w) red[tid] += red[tid + w];
        __syncthreads();
    }
    if (tid == 0)
        g_emd[s] = (t == 0) ? red[0] * (1.0f / ((float)BQ * NPTS * 2)) : 0.0f;

    // Histogram (counts order-invariant).
    if (tid < NBINS) hist[tid] = 0;
    __syncthreads();
    for (int i = tid; i < NPTS; i += PTHREADS)
        atomicAdd(&hist[binOf(src[i].x)], 1);
    __syncthreads();

    // Inclusive scan over 512 bins (Hillis–Steele).
    if (tid < NBINS) scn[tid] = hist[tid];
    __syncthreads();
    for (int off = 1; off < NBINS; off <<= 1) {
        int v = 0;
        if (tid < NBINS && tid >= off) v = scn[tid - off];
        __syncthreads();
        if (tid < NBINS) scn[tid] += v;
        __syncthreads();
    }
    if (tid == 0) start[0] = 0;
    if (tid < NBINS) start[tid + 1] = scn[tid];
    __syncthreads();                           // start[] complete before cursors
    if (tid < NBINS) hist[tid] = start[tid];   // cursors
    __syncthreads();

    // Scatter with original index carried.
    for (int i = tid; i < NPTS; i += PTHREADS) {
        const float2 p = src[i];
        const int bb = binOf(p.x);
        const int pos = atomicAdd(&hist[bb], 1);
        g_pts[s][pos]  = p;
        g_sidx[s][pos] = i;
    }
    for (int i = tid; i <= NBINS; i += PTHREADS)
        g_binStart[s][i] = start[i];
}

// ───────── Kernel B: exact NN, fixed pipelined window + BIN-EDGE certificate ─
// Thread t owns sorted-slot query blockIdx.x*512 + t. Fixed WIN-candidate scan
// (unrollable, latency-hidden); certificate uses bin edges, which bound |dx|
// for ALL unscanned points regardless of within-bin order (exact).
__global__ __launch_bounds__(STHREADS, 1)
void search_kernel(float* __restrict__ outDummy) {
    __shared__ float2         shPts[NPTS];        // 32 KB: bin-sorted refs
    __shared__ unsigned short shBin[NPTS];        //  8 KB: slot -> bin id
    __shared__ int            shStart[NBINS + 1]; //  2 KB

    const int tid = threadIdx.x;
    const int dir = blockIdx.z;
    const int b   = blockIdx.y;
    const int sq  = (b << 1) | dir;          // query set
    const int sr  = (b << 1) | (1 - dir);    // reference set

    for (int i = tid; i < NPTS; i += STHREADS) shPts[i] = g_pts[sr][i];
    for (int i = tid; i <= NBINS; i += STHREADS) shStart[i] = g_binStart[sr][i];
    __syncthreads();
    // slot -> bin map (thread i fills bin i's span; spans are small).
    if (tid < NBINS) {
        const int e0 = shStart[tid], e1 = shStart[tid + 1];
        for (int j = e0; j < e1; j++) shBin[j] = (unsigned short)tid;
    }
    __syncthreads();

    const int slot = blockIdx.x * STHREADS + tid;
    const float2 q = g_pts[sq][slot];
    const int    oi = g_sidx[sq][slot];
    const int qb = binOf(q.x);

    // Fixed window centered on the home bin's middle.
    const int mid = (shStart[qb] + shStart[qb + 1]) >> 1;
    const int s0  = min(max(mid - WIN / 2, 0), NPTS - WIN);

    float best = 1e30f;
#pragma unroll 16
    for (int j = 0; j < WIN; j++) {
        const float2 r = shPts[s0 + j];
        const float dx = r.x - q.x, dy = r.y - q.y;
        best = fminf(best, fmaf(dx, dx, dy * dy));
    }

    // Bin-edge certificate (valid for arbitrary within-bin order):
    //   any slot < lo  is in bin <= shBin[lo-1], so x <  binEdge(shBin[lo-1]+1)
    //   any slot >= hi is in bin >= shBin[hi],   so x >= binEdge(shBin[hi])
    int lo = s0, hi = s0 + WIN;   // scanned = [lo, hi)
    for (;;) {
        const float gl = (lo > 0)    ? (q.x - binEdge((int)shBin[lo - 1] + 1)) : 1e30f;
        const float gr = (hi < NPTS) ? (binEdge((int)shBin[hi]) - q.x)         : 1e30f;
        const bool okL = (gl >= 0.0f) && (gl * gl >= best);
        const bool okR = (gr >= 0.0f) && (gr * gr >= best);
        if (okL && okR) break;
        // Extend the side that is not yet certified (prefer the nearer one).
        if (!okL && (okR || gl <= gr)) {
            lo--;
            const float2 r = shPts[lo];
            const float dx = r.x - q.x, dy = r.y - q.y;
            best = fminf(best, fmaf(dx, dx, dy * dy));
        } else {
            const float2 r = shPts[hi];
            const float dx = r.x - q.x, dy = r.y - q.y;
            best = fminf(best, fmaf(dx, dx, dy * dy));
            hi++;
        }
    }

    // Deterministic destination: original index. best == exact global NN d^2.
    g_best[sq][oi] = best;
}

// ───────── Kernel C: fixed-order final sum (bit-deterministic) ───────────────
__global__ __launch_bounds__(FTHREADS, 1)
void finalize_kernel(float* __restrict__ out) {
    __shared__ float red[FTHREADS];
    const int tid = threadIdx.x;

    float acc = 0.0f;
    const float* bb = &g_best[0][0];
    for (int k = tid; k < NSETS * NPTS; k += FTHREADS) acc += bb[k];
    red[tid] = acc;
    __syncthreads();
    for (int w = FTHREADS / 2; w > 0; w >>= 1) {
        if (tid < w) red[tid] += red[tid + w];
        __syncthreads();
    }
    if (tid == 0) {
        float total = red[0] * (1.0f / BQ);
        for (int s = 0; s < NSETS; s++) total += g_emd[s];
        out[0] = total;
    }
}

extern "C" void kernel_launch(void* const* d_in, const int* in_sizes, int n_in,
                              void* d_out, int out_size) {
    const float* y_true = (const float*)d_in[0];
    const float* y_pred = (const float*)d_in[1];
    float* out = (float*)d_out;

    prep_kernel<<<NSETS, PTHREADS>>>(y_true, y_pred);
    dim3 grid(NPTS / STHREADS, BQ, 2);   // (8, 8, 2)
    search_kernel<<<grid, STHREADS>>>(out);
    finalize_kernel<<<1, FTHREADS>>>(out);
}